// round 3
// baseline (speedup 1.0000x reference)
#include <cuda_runtime.h>
#include <cuda_bf16.h>

#define Bsz  512
#define Ssz  1024
#define Esz  48
#define Hsz  128
#define NCLS 2000
#define BC   4      // batch rows per CTA
#define KC   52     // k-slices of w_hh cached in smem (must be even)
#define NSCH ((Hsz - KC) / 4)   // streamed 4-k chunks = 19

// Packed parameter storage (prepared once per launch by prep_kernel).
// g_wPack  : [gp][k][j][gi]   gp=gate-pair (0:i,f  1:g,o), gi in {0,1}
// g_wIhPack: [gp][e][j][gi]
// g_bias   : [gp][j][gi]      (= b_ih + b_hh)
// g_wfcT   : [k][n]
__device__ float g_wPack  [2 * Hsz * Hsz * 2];
__device__ float g_wIhPack[2 * Esz * Hsz * 2];
__device__ float g_bias   [2 * Hsz * 2];
__device__ float g_wfcT   [Hsz * NCLS];
__device__ float g_hfin   [Bsz * Hsz];

typedef unsigned long long ull;

__device__ __forceinline__ void ffma2(ull& acc, ull a, ull b) {
    // packed f32x2 FMA: acc = a * b + acc  (two fp32 lanes per instruction)
    asm("fma.rn.f32x2 %0, %1, %2, %0;" : "+l"(acc) : "l"(a), "l"(b));
}
__device__ __forceinline__ ull f2u(float2 v) {
    ull r; asm("mov.b64 %0, {%1, %2};" : "=l"(r) : "f"(v.x), "f"(v.y)); return r;
}
__device__ __forceinline__ float2 u2f(ull v) {
    float2 r; asm("mov.b64 {%0, %1}, %2;" : "=f"(r.x), "=f"(r.y) : "l"(v)); return r;
}

__device__ __forceinline__ float sigf(float x) {
    return __fdividef(1.0f, 1.0f + __expf(-x));
}
__device__ __forceinline__ float tanf_(float x) {
    float e = __expf(-2.0f * x);
    return __fdividef(1.0f - e, 1.0f + e);
}

// ---------------------------------------------------------------------------
// Prep: transpose/pack weights (idempotent, runs every launch).
// ---------------------------------------------------------------------------
__global__ void prep_kernel(const float* __restrict__ w_ih, const float* __restrict__ w_hh,
                            const float* __restrict__ b_ih, const float* __restrict__ b_hh,
                            const float* __restrict__ w_fc) {
    int i = blockIdx.x * blockDim.x + threadIdx.x;
    if (i < 2 * Hsz * Hsz * 2) {
        int gi = i & 1, j = (i >> 1) & 127, k = (i >> 8) & 127, gp = i >> 15;
        g_wPack[i] = w_hh[((gp * 2 + gi) * Hsz + j) * Hsz + k];
    }
    if (i < 2 * Esz * Hsz * 2) {
        int gi = i & 1, j = (i >> 1) & 127;
        int t = i >> 8;
        int e = t % Esz, gp = t / Esz;
        g_wIhPack[i] = w_ih[((gp * 2 + gi) * Hsz + j) * Esz + e];
    }
    if (i < 2 * Hsz * 2) {
        int gi = i & 1, j = (i >> 1) & 127, gp = i >> 8;
        int r = (gp * 2 + gi) * Hsz + j;
        g_bias[i] = b_ih[r] + b_hh[r];
    }
    if (i < Hsz * NCLS) {
        int k = i / NCLS, n = i % NCLS;
        g_wfcT[i] = w_fc[n * Hsz + k];
    }
}

// ---------------------------------------------------------------------------
// LSTM recurrence, f32x2 edition.
// Thread (gp, j) accumulates gates (2gp, 2gp+1) for 4 batch rows, each as one
// packed f32x2 accumulator:  acc_b += (w_gi0, w_gi1) * (h_k, h_k).
// h is stored DUPLICATED in smem as float2 (h,h) so an LDS.128 yields two
// ready-made f32x2 operands for consecutive k.
// ---------------------------------------------------------------------------
struct alignas(16) Smem {
    float  wih[2 * Esz * Hsz * 2];   // 96 KB  (full w_ih, gi-paired)
    float  whh[2 * KC  * Hsz * 2];   // 104 KB (k < KC slice, gi-paired)
    float2 hd[BC][Hsz];              // 4 KB   h duplicated (h,h)
    float  c[BC][Hsz];               // 2 KB
    float2 gbuf[2][BC][Hsz];         // 8 KB   [gp][bc][j] = (gate_2gp, gate_2gp+1)
    float2 ed[2][BC][Esz];           // 3 KB   embeddings duplicated, double-buffered
};

// 8 packed FMAs for one k-pair across 4 batches. HP = ulonglong2* into hd[bc].
#define KPAIR(W2A, W2B, KP)                                        \
    do {                                                           \
        const ulonglong2 hv0 = *(const ulonglong2*)&s->hd[0][(KP) * 2]; \
        const ulonglong2 hv1 = *(const ulonglong2*)&s->hd[1][(KP) * 2]; \
        const ulonglong2 hv2 = *(const ulonglong2*)&s->hd[2][(KP) * 2]; \
        const ulonglong2 hv3 = *(const ulonglong2*)&s->hd[3][(KP) * 2]; \
        ffma2(a0, (W2A), hv0.x); ffma2(a1, (W2A), hv1.x);          \
        ffma2(a2, (W2A), hv2.x); ffma2(a3, (W2A), hv3.x);          \
        ffma2(a0, (W2B), hv0.y); ffma2(a1, (W2B), hv1.y);          \
        ffma2(a2, (W2B), hv2.y); ffma2(a3, (W2B), hv3.y);          \
    } while (0)

__global__ void __launch_bounds__(256, 1)
lstm_kernel(const int* __restrict__ x, const float* __restrict__ emb) {
    extern __shared__ char smem_raw[];
    Smem* s = reinterpret_cast<Smem*>(smem_raw);

    const int tid = threadIdx.x;
    const int j   = tid & 127;
    const int gp  = tid >> 7;
    const int b0  = blockIdx.x * BC;

    // Stage packed weights into smem.
    for (int i = tid; i < 2 * Esz * Hsz * 2; i += 256) s->wih[i] = g_wIhPack[i];
    for (int g = 0; g < 2; g++)
        for (int i = tid; i < KC * Hsz * 2; i += 256)
            s->whh[g * (KC * 256) + i] = g_wPack[g * (Hsz * 256) + i];
    for (int i = tid; i < BC * Hsz; i += 256) {
        s->hd[i >> 7][i & 127] = make_float2(0.0f, 0.0f);
        s->c[i >> 7][i & 127]  = 0.0f;
    }
    __syncthreads();

    // Embedding prefetch lanes: 192 threads, one (bc, e) element each.
    const int  bcp = tid / Esz;
    const int  eep = tid - bcp * Esz;
    const bool eTh = (tid < BC * Esz);
    int tv = 0;                       // token for step s+1 (register pipeline)
    if (eTh) {
        const int t0 = __ldg(&x[(b0 + bcp) * Ssz + 0]);
        const float e0 = __ldg(&emb[t0 * Esz + eep]);
        s->ed[0][bcp][eep] = make_float2(e0, e0);
        tv = __ldg(&x[(b0 + bcp) * Ssz + 1]);
    }

    const float2 bias2 = *(const float2*)(g_bias + (gp * Hsz + j) * 2);
    const ull    biasU = f2u(bias2);
    const float* __restrict__ wHs = s->whh + gp * (KC * 256) + j * 2;               // k in [0,KC)
    const float* __restrict__ wHg = g_wPack + gp * (Hsz * 256) + KC * 256 + j * 2;  // k in [KC,128)
    const float* __restrict__ wIs = s->wih + gp * (Esz * 256) + j * 2;
    __syncthreads();

    for (int st = 0; st < Ssz; st++) {
        const int buf = st & 1;

        // Prefetch next step's embedding row + token after that.
        float ev = 0.0f;
        const bool doE = eTh && (st + 1 < Ssz);
        if (doE) ev = __ldg(&emb[tv * Esz + eep]);
        int tvn = 0;
        if (eTh && (st + 2 < Ssz)) tvn = __ldg(&x[(b0 + bcp) * Ssz + st + 2]);

        ull a0 = biasU, a1 = biasU, a2 = biasU, a3 = biasU;

        // --- recurrent GEMV, smem-cached k in [0, KC) ---
        #pragma unroll
        for (int kp = 0; kp < KC / 2; kp++) {
            const ull w2a = f2u(*(const float2*)(wHs + (kp * 2 + 0) * 256));
            const ull w2b = f2u(*(const float2*)(wHs + (kp * 2 + 1) * 256));
            KPAIR(w2a, w2b, kp);
        }

        // --- recurrent GEMV, L2-streamed k in [KC, 128): double-buffered LDG ---
        {
            float2 wpre[2][4];
            #pragma unroll
            for (int q = 0; q < 4; q++)
                wpre[0][q] = *(const float2*)(wHg + q * 256);
            #pragma unroll
            for (int t = 0; t < NSCH; t++) {
                const int cur = t & 1;
                if (t + 1 < NSCH) {
                    #pragma unroll
                    for (int q = 0; q < 4; q++)
                        wpre[cur ^ 1][q] = *(const float2*)(wHg + ((t + 1) * 4 + q) * 256);
                }
                #pragma unroll
                for (int p = 0; p < 2; p++) {
                    const ull w2a = f2u(wpre[cur][p * 2 + 0]);
                    const ull w2b = f2u(wpre[cur][p * 2 + 1]);
                    KPAIR(w2a, w2b, KC / 2 + t * 2 + p);
                }
            }
        }

        // --- input GEMV (fused embedding), e in [0, 48), weights in smem ---
        #pragma unroll
        for (int ep = 0; ep < Esz / 2; ep++) {
            const ull w2a = f2u(*(const float2*)(wIs + (ep * 2 + 0) * 256));
            const ull w2b = f2u(*(const float2*)(wIs + (ep * 2 + 1) * 256));
            const ulonglong2 ev0 = *(const ulonglong2*)&s->ed[buf][0][ep * 2];
            const ulonglong2 ev1 = *(const ulonglong2*)&s->ed[buf][1][ep * 2];
            const ulonglong2 ev2 = *(const ulonglong2*)&s->ed[buf][2][ep * 2];
            const ulonglong2 ev3 = *(const ulonglong2*)&s->ed[buf][3][ep * 2];
            ffma2(a0, w2a, ev0.x); ffma2(a1, w2a, ev1.x);
            ffma2(a2, w2a, ev2.x); ffma2(a3, w2a, ev3.x);
            ffma2(a0, w2b, ev0.y); ffma2(a1, w2b, ev1.y);
            ffma2(a2, w2b, ev2.y); ffma2(a3, w2b, ev3.y);
        }

        // Publish pre-activations (gate pair packed in float2).
        s->gbuf[gp][0][j] = u2f(a0);
        s->gbuf[gp][1][j] = u2f(a1);
        s->gbuf[gp][2][j] = u2f(a2);
        s->gbuf[gp][3][j] = u2f(a3);
        __syncthreads();

        // Gate combine: 512 cells over 256 threads, 2 each.
        #pragma unroll
        for (int r = 0; r < 2; r++) {
            const int idx = tid + r * 256;
            const int bc = idx >> 7, jj = idx & 127;
            const float2 gif = s->gbuf[0][bc][jj];   // (i, f)
            const float2 ggo = s->gbuf[1][bc][jj];   // (g, o)
            const float iv = sigf(gif.x);
            const float fv = sigf(gif.y);
            const float gv = tanf_(ggo.x);
            const float ov = sigf(ggo.y);
            const float cv = fv * s->c[bc][jj] + iv * gv;
            s->c[bc][jj] = cv;
            const float hv = ov * tanf_(cv);
            s->hd[bc][jj] = make_float2(hv, hv);
        }
        if (doE) s->ed[buf ^ 1][bcp][eep] = make_float2(ev, ev);
        tv = tvn;
        __syncthreads();
    }

    // Export final hidden state.
    for (int i = tid; i < BC * Hsz; i += 256)
        g_hfin[(b0 + (i >> 7)) * Hsz + (i & 127)] = s->hd[i >> 7][i & 127].x;
}

// ---------------------------------------------------------------------------
// FC epilogue: out[b][n] = h_fin[b] . w_fc[n] + b_fc[n]
// ---------------------------------------------------------------------------
__global__ void fc_kernel(const float* __restrict__ b_fc, float* __restrict__ out) {
    __shared__ float hs[8][Hsz];
    const int tid = threadIdx.x;
    const int n   = blockIdx.x * 128 + tid;
    const int bb  = blockIdx.y * 8;
    for (int i = tid; i < 8 * Hsz; i += 128)
        hs[i >> 7][i & 127] = g_hfin[(bb + (i >> 7)) * Hsz + (i & 127)];
    __syncthreads();
    if (n >= NCLS) return;
    const float bv = b_fc[n];
    float acc[8];
    #pragma unroll
    for (int i = 0; i < 8; i++) acc[i] = bv;
    #pragma unroll 4
    for (int k = 0; k < Hsz; k++) {
        const float w = g_wfcT[k * NCLS + n];
        #pragma unroll
        for (int i = 0; i < 8; i++) acc[i] = fmaf(hs[i][k], w, acc[i]);
    }
    #pragma unroll
    for (int i = 0; i < 8; i++) out[(bb + i) * NCLS + n] = acc[i];
}

extern "C" void kernel_launch(void* const* d_in, const int* in_sizes, int n_in,
                              void* d_out, int out_size) {
    const int*   x    = (const int*)  d_in[0];
    const float* emb  = (const float*)d_in[1];
    const float* w_ih = (const float*)d_in[2];
    const float* w_hh = (const float*)d_in[3];
    const float* b_ih = (const float*)d_in[4];
    const float* b_hh = (const float*)d_in[5];
    const float* w_fc = (const float*)d_in[6];
    const float* b_fc = (const float*)d_in[7];
    float* out = (float*)d_out;

    static bool attr_set = false;
    if (!attr_set) {
        cudaFuncSetAttribute(lstm_kernel, cudaFuncAttributeMaxDynamicSharedMemorySize,
                             (int)sizeof(Smem));
        attr_set = true;
    }

    prep_kernel<<<1000, 256>>>(w_ih, w_hh, b_ih, b_hh, w_fc);
    lstm_kernel<<<Bsz / BC, 256, sizeof(Smem)>>>(x, emb);
    fc_kernel<<<dim3((NCLS + 127) / 128, Bsz / 8), 128>>>(b_fc, out);
}

// round 5
// speedup vs baseline: 1.3897x; 1.3897x over previous
#include <cuda_runtime.h>
#include <cuda_bf16.h>

#define Bsz  512
#define Ssz  1024
#define Esz  48
#define Hsz  128
#define NCLS 2000
#define BC   4              // batch rows per CTA
#define KPC  26             // cached k-pairs (k < 52 in smem)
#define NKP  64             // total k-pairs
#define NSP  (NKP - KPC)    // streamed k-pairs = 38
#define EP   24             // e-pairs

// Packed parameter storage (prepared once per launch by prep_kernel).
// g_wKpack: [gp][kp][j][q]  q = (gate_lo_k, gate_lo_k+1, gate_hi_k, gate_hi_k+1)
//           gate_lo = 2gp, gate_hi = 2gp+1, k = 2*kp
// g_wIK   : [gp][ep][j][q]  same, e = 2*ep
// g_bias  : [gp][j][gi]     (= b_ih + b_hh)
__device__ float g_wKpack[2 * NKP * Hsz * 4];
__device__ float g_wIK   [2 * EP  * Hsz * 4];
__device__ float g_bias  [2 * Hsz * 2];
__device__ float g_wfcT  [Hsz * NCLS];
__device__ float g_hfin  [Bsz * Hsz];

typedef unsigned long long ull;

__device__ __forceinline__ void ffma2(ull& acc, ull a, ull b) {
    asm("fma.rn.f32x2 %0, %1, %2, %0;" : "+l"(acc) : "l"(a), "l"(b));
}
__device__ __forceinline__ ull f2u2(float x, float y) {
    ull r; asm("mov.b64 %0, {%1, %2};" : "=l"(r) : "f"(x), "f"(y)); return r;
}
__device__ __forceinline__ float2 u2f(ull v) {
    float2 r; asm("mov.b64 {%0, %1}, %2;" : "=f"(r.x), "=f"(r.y) : "l"(v)); return r;
}
__device__ __forceinline__ float sigf(float x) {
    return __fdividef(1.0f, 1.0f + __expf(-x));
}
__device__ __forceinline__ float tanf_(float x) {
    float e = __expf(-2.0f * x);
    return __fdividef(1.0f - e, 1.0f + e);
}

// ---------------------------------------------------------------------------
__global__ void prep_kernel(const float* __restrict__ w_ih, const float* __restrict__ w_hh,
                            const float* __restrict__ b_ih, const float* __restrict__ b_hh,
                            const float* __restrict__ w_fc) {
    int i = blockIdx.x * blockDim.x + threadIdx.x;
    if (i < 2 * NKP * Hsz * 4) {
        int q = i & 3, j = (i >> 2) & 127, kp = (i >> 9) & 63, gp = (i >> 15) & 1;
        int gate = gp * 2 + (q >> 1);
        int k = kp * 2 + (q & 1);
        g_wKpack[i] = w_hh[(gate * Hsz + j) * Hsz + k];
    }
    if (i < 2 * EP * Hsz * 4) {
        int q = i & 3, j = (i >> 2) & 127;
        int rest = i >> 9;                 // [0, 48)
        int ep = rest % EP, gp = rest / EP;
        int gate = gp * 2 + (q >> 1);
        int e = ep * 2 + (q & 1);
        g_wIK[i] = w_ih[(gate * Hsz + j) * Esz + e];
    }
    if (i < 2 * Hsz * 2) {
        int gi = i & 1, j = (i >> 1) & 127, gp = i >> 8;
        int r = (gp * 2 + gi) * Hsz + j;
        g_bias[i] = b_ih[r] + b_hh[r];
    }
    if (i < Hsz * NCLS) {
        int k = i / NCLS, n = i % NCLS;
        g_wfcT[i] = w_fc[n * Hsz + k];
    }
}

// ---------------------------------------------------------------------------
// LSTM recurrence. Thread (gp, j): gates (2gp, 2gp+1) x 4 batches.
// f32x2 packed along k: acc lanes = (sum over even k, sum over odd k).
// ---------------------------------------------------------------------------
struct alignas(16) Smem {
    float  wih[2 * EP  * Hsz * 4];   //  96 KB
    float  whh[2 * KPC * Hsz * 4];   // 104 KB (k-pairs < KPC)
    float  h[BC][Hsz];               //   2 KB
    float  c[BC][Hsz];               //   2 KB
    float2 gbuf[2][BC][Hsz];         //   8 KB  [gp][bc][j] = (g_2gp, g_2gp+1)
    float  e[2][BC][Esz];            // 1.5 KB  double-buffered embeddings
};

struct Acc8 {
    ull a00, a01, a02, a03, a10, a11, a12, a13;
};

// One k-pair (or e-pair): packed weight float4 w, packed operands o0..o3.
__device__ __forceinline__ void kp2(Acc8& A, float4 w, ull o0, ull o1, ull o2, ull o3) {
    const ull pA = f2u2(w.x, w.y);
    const ull pB = f2u2(w.z, w.w);
    ffma2(A.a00, pA, o0); ffma2(A.a01, pA, o1);
    ffma2(A.a02, pA, o2); ffma2(A.a03, pA, o3);
    ffma2(A.a10, pB, o0); ffma2(A.a11, pB, o1);
    ffma2(A.a12, pB, o2); ffma2(A.a13, pB, o3);
}

__global__ void __launch_bounds__(256, 1)
lstm_kernel(const int* __restrict__ x, const float* __restrict__ emb) {
    extern __shared__ char smem_raw[];
    Smem* s = reinterpret_cast<Smem*>(smem_raw);

    const int tid = threadIdx.x;
    const int j   = tid & 127;
    const int gp  = tid >> 7;
    const int b0  = blockIdx.x * BC;

    // Stage packed weights into smem.
    for (int i = tid; i < 2 * EP * Hsz * 4; i += 256) s->wih[i] = g_wIK[i];
    for (int g = 0; g < 2; g++)
        for (int i = tid; i < KPC * Hsz * 4; i += 256)
            s->whh[g * (KPC * 512) + i] = g_wKpack[g * (NKP * 512) + i];
    for (int i = tid; i < BC * Hsz; i += 256) {
        s->h[i >> 7][i & 127] = 0.0f;
        s->c[i >> 7][i & 127] = 0.0f;
    }
    __syncthreads();

    // Embedding prefetch lanes: 192 threads, one (bc, e) element each.
    const int  bcp = tid / Esz;
    const int  eep = tid - bcp * Esz;
    const bool eTh = (tid < BC * Esz);
    int tv = 0;
    if (eTh) {
        const int t0 = __ldg(&x[(b0 + bcp) * Ssz + 0]);
        s->e[0][bcp][eep] = __ldg(&emb[t0 * Esz + eep]);
        tv = __ldg(&x[(b0 + bcp) * Ssz + 1]);
    }

    const float2 b2 = *(const float2*)(g_bias + (gp * Hsz + j) * 2);
    const ull bias0 = f2u2(b2.x, 0.0f);
    const ull bias1 = f2u2(b2.y, 0.0f);
    const float* __restrict__ wcH = s->whh    + gp * (KPC * 512) + j * 4;
    const float* __restrict__ wgH = g_wKpack  + (gp * NKP + KPC) * 512 + j * 4;
    const float* __restrict__ wcI = s->wih    + gp * (EP * 512) + j * 4;
    __syncthreads();

    for (int st = 0; st < Ssz; st++) {
        const int buf = st & 1;

        // Prefetch next step's embedding row + token after that.
        float ev = 0.0f;
        const bool doE = eTh && (st + 1 < Ssz);
        if (doE) ev = __ldg(&emb[tv * Esz + eep]);
        int tvn = 0;
        if (eTh && (st + 2 < Ssz)) tvn = __ldg(&x[(b0 + bcp) * Ssz + st + 2]);

        Acc8 A;
        A.a00 = bias0; A.a01 = bias0; A.a02 = bias0; A.a03 = bias0;
        A.a10 = bias1; A.a11 = bias1; A.a12 = bias1; A.a13 = bias1;

        // Start the streamed-weight pipeline early (lands during cached work).
        float4 wq[8];
        #pragma unroll
        for (int q = 0; q < 8; q++)
            wq[q] = *(const float4*)(wgH + q * 512);

        // --- recurrent GEMV, smem-cached k-pairs [0, KPC) ---
        #pragma unroll
        for (int g2 = 0; g2 < KPC / 2; g2++) {
            const ulonglong2 h0 = *(const ulonglong2*)&s->h[0][g2 * 4];
            const ulonglong2 h1 = *(const ulonglong2*)&s->h[1][g2 * 4];
            const ulonglong2 h2 = *(const ulonglong2*)&s->h[2][g2 * 4];
            const ulonglong2 h3 = *(const ulonglong2*)&s->h[3][g2 * 4];
            const float4 wA = *(const float4*)(wcH + (2 * g2 + 0) * 512);
            const float4 wB = *(const float4*)(wcH + (2 * g2 + 1) * 512);
            kp2(A, wA, h0.x, h1.x, h2.x, h3.x);
            kp2(A, wB, h0.y, h1.y, h2.y, h3.y);
        }

        // --- input GEMV (fused embedding), e-pairs in smem ---
        #pragma unroll
        for (int g2 = 0; g2 < EP / 2; g2++) {
            const ulonglong2 e0 = *(const ulonglong2*)&s->e[buf][0][g2 * 4];
            const ulonglong2 e1 = *(const ulonglong2*)&s->e[buf][1][g2 * 4];
            const ulonglong2 e2 = *(const ulonglong2*)&s->e[buf][2][g2 * 4];
            const ulonglong2 e3 = *(const ulonglong2*)&s->e[buf][3][g2 * 4];
            const float4 wA = *(const float4*)(wcI + (2 * g2 + 0) * 512);
            const float4 wB = *(const float4*)(wcI + (2 * g2 + 1) * 512);
            kp2(A, wA, e0.x, e1.x, e2.x, e3.x);
            kp2(A, wB, e0.y, e1.y, e2.y, e3.y);
        }

        // --- recurrent GEMV, L2-streamed k-pairs [KPC, 64): rolling depth-8 ---
        #pragma unroll
        for (int t = 0; t < NSP / 2; t++) {          // 19 groups of 2 k-pairs
            const int kp = 2 * t;
            const ulonglong2 h0 = *(const ulonglong2*)&s->h[0][2 * KPC + t * 4];
            const ulonglong2 h1 = *(const ulonglong2*)&s->h[1][2 * KPC + t * 4];
            const ulonglong2 h2 = *(const ulonglong2*)&s->h[2][2 * KPC + t * 4];
            const ulonglong2 h3 = *(const ulonglong2*)&s->h[3][2 * KPC + t * 4];
            const float4 wA = wq[(kp + 0) & 7];
            const float4 wB = wq[(kp + 1) & 7];
            if (kp + 8 < NSP) wq[(kp + 0) & 7] = *(const float4*)(wgH + (kp + 8) * 512);
            if (kp + 9 < NSP) wq[(kp + 1) & 7] = *(const float4*)(wgH + (kp + 9) * 512);
            kp2(A, wA, h0.x, h1.x, h2.x, h3.x);
            kp2(A, wB, h0.y, h1.y, h2.y, h3.y);
        }

        // Publish pre-activations: gate value = lane.x + lane.y.
        {
            const float2 r00 = u2f(A.a00), r01 = u2f(A.a01), r02 = u2f(A.a02), r03 = u2f(A.a03);
            const float2 r10 = u2f(A.a10), r11 = u2f(A.a11), r12 = u2f(A.a12), r13 = u2f(A.a13);
            s->gbuf[gp][0][j] = make_float2(r00.x + r00.y, r10.x + r10.y);
            s->gbuf[gp][1][j] = make_float2(r01.x + r01.y, r11.x + r11.y);
            s->gbuf[gp][2][j] = make_float2(r02.x + r02.y, r12.x + r12.y);
            s->gbuf[gp][3][j] = make_float2(r03.x + r03.y, r13.x + r13.y);
        }
        __syncthreads();

        // Gate combine: 512 cells over 256 threads, 2 each.
        #pragma unroll
        for (int r = 0; r < 2; r++) {
            const int idx = tid + r * 256;
            const int bc = idx >> 7, jj = idx & 127;
            const float2 gif = s->gbuf[0][bc][jj];   // (i, f)
            const float2 ggo = s->gbuf[1][bc][jj];   // (g, o)
            const float iv = sigf(gif.x);
            const float fv = sigf(gif.y);
            const float gv = tanf_(ggo.x);
            const float ov = sigf(ggo.y);
            const float cv = fv * s->c[bc][jj] + iv * gv;
            s->c[bc][jj] = cv;
            s->h[bc][jj] = ov * tanf_(cv);
        }
        if (doE) s->e[buf ^ 1][bcp][eep] = ev;
        tv = tvn;
        __syncthreads();
    }

    // Export final hidden state.
    for (int i = tid; i < BC * Hsz; i += 256)
        g_hfin[(b0 + (i >> 7)) * Hsz + (i & 127)] = s->h[i >> 7][i & 127];
}

// ---------------------------------------------------------------------------
// FC epilogue: out[b][n] = h_fin[b] . w_fc[n] + b_fc[n]
// ---------------------------------------------------------------------------
__global__ void fc_kernel(const float* __restrict__ b_fc, float* __restrict__ out) {
    __shared__ float hs[8][Hsz];
    const int tid = threadIdx.x;
    const int n   = blockIdx.x * 128 + tid;
    const int bb  = blockIdx.y * 8;
    for (int i = tid; i < 8 * Hsz; i += 128)
        hs[i >> 7][i & 127] = g_hfin[(bb + (i >> 7)) * Hsz + (i & 127)];
    __syncthreads();
    if (n >= NCLS) return;
    const float bv = b_fc[n];
    float acc[8];
    #pragma unroll
    for (int i = 0; i < 8; i++) acc[i] = bv;
    #pragma unroll 4
    for (int k = 0; k < Hsz; k++) {
        const float w = g_wfcT[k * NCLS + n];
        #pragma unroll
        for (int i = 0; i < 8; i++) acc[i] = fmaf(hs[i][k], w, acc[i]);
    }
    #pragma unroll
    for (int i = 0; i < 8; i++) out[(bb + i) * NCLS + n] = acc[i];
}

extern "C" void kernel_launch(void* const* d_in, const int* in_sizes, int n_in,
                              void* d_out, int out_size) {
    const int*   x    = (const int*)  d_in[0];
    const float* emb  = (const float*)d_in[1];
    const float* w_ih = (const float*)d_in[2];
    const float* w_hh = (const float*)d_in[3];
    const float* b_ih = (const float*)d_in[4];
    const float* b_hh = (const float*)d_in[5];
    const float* w_fc = (const float*)d_in[6];
    const float* b_fc = (const float*)d_in[7];
    float* out = (float*)d_out;

    static bool attr_set = false;
    if (!attr_set) {
        cudaFuncSetAttribute(lstm_kernel, cudaFuncAttributeMaxDynamicSharedMemorySize,
                             (int)sizeof(Smem));
        attr_set = true;
    }

    prep_kernel<<<1000, 256>>>(w_ih, w_hh, b_ih, b_hh, w_fc);
    lstm_kernel<<<Bsz / BC, 256, sizeof(Smem)>>>(x, emb);
    fc_kernel<<<dim3((NCLS + 127) / 128, Bsz / 8), 128>>>(b_fc, out);
}